// round 11
// baseline (speedup 1.0000x reference)
#include <cuda_runtime.h>

#define E_TOT   32768
#define NN      2048
#define D       128
#define DF      32
#define DC      160
#define PJ      130   // weight shared pitch (conflict-free LDS.64)
#define EPS     16    // edges per sub (16 floats = 64B row; 2 rows = one 128B block)
#define TEB     64    // tile edges per block (4 subs x EPS)
#define GRID_MLP 152  // one persistent CTA per GB300 SM
#define NTILE   (E_TOT / TEB)   // 512 edge tiles

// Scratch (device globals: no allocations allowed)
__device__ float    g_s[E_TOT * D];        // 16 MB
__device__ float    g_cat[E_TOT * DC];     // 21 MB
__device__ float    g_node[NN * D];        // 1 MB (L2-resident)
__device__ unsigned g_bits[NN * (E_TOT / 32)];   // 8 MB  node-major bitmask
__device__ unsigned g_bitsT[(NN / 32) * E_TOT];  // 8 MB  [node-word j][edge e]

typedef unsigned long long u64;

__device__ __forceinline__ u64 pk2(float lo, float hi) {
    u64 r; asm("mov.b64 %0, {%1,%2};" : "=l"(r) : "f"(lo), "f"(hi)); return r;
}
__device__ __forceinline__ void upk2(u64 v, float& lo, float& hi) {
    asm("mov.b64 {%0,%1}, %2;" : "=f"(lo), "=f"(hi) : "l"(v));
}
// Packed fp32x2 FMA — 2x FFMA throughput on sm_103a (FFMA2), only via PTX.
__device__ __forceinline__ u64 fma2(u64 a, u64 b, u64 c) {
    u64 d; asm("fma.rn.f32x2 %0, %1, %2, %3;" : "=l"(d) : "l"(a), "l"(b), "l"(c)); return d;
}

// log_sigmoid(x) = min(x,0) - log1p(exp(-|x|))  (stable, matches jax.nn.log_sigmoid)
__device__ __forceinline__ float lsig(float x) {
    return fminf(x, 0.0f) - log1pf(__expf(-fabsf(x)));
}

// Swizzled chunk offset (in floats) for row i, 16B-chunk c, within a sub's
// region: block = i>>1 (2 rows = 32 floats = 128B), slot = ((i&1)*4 + c) ^ (block&7).
// Writes spread across all 32 banks (floor wavefronts); reads are broadcasts
// with compile-time offsets when the i-loop is unrolled by 16.
#define XOFF(i, c) (((i) >> 1) * 32 + 4 * (((((i) & 1) << 2) | (c)) ^ (((i) >> 1) & 7)))

// ---------------------------------------------------------------------------
// Persistent fused 2-layer MLP:  out = lsig( lsig(X @ W1^T + b1) @ W2^T )
// Grid = 152 CTAs (1/SM). Weights staged to shared ONCE; each CTA strides
// over 64-edge tiles. Block = 256 threads = 4 subs x 64 j2-threads; each
// sub owns 16 edges (8 f32x2 packs). xs/hp use the XOR-swizzled chunk
// layout -> all smem store phases at crossbar floor.
// STREAM_OUT: stores use STG.CS (final output, never re-read on-device).
// ---------------------------------------------------------------------------
template <int DI, bool STREAM_OUT>
__global__ void __launch_bounds__(256) k_mlp(const float* __restrict__ X,
                                             const float* __restrict__ W1,
                                             const float* __restrict__ b1,
                                             const float* __restrict__ W2,
                                             float* __restrict__ out)
{
    extern __shared__ float sm[];
    float* W1t = sm;                        // DI * PJ
    float* W2t = W1t + DI * PJ;             // 128 * PJ
    float* xs  = W2t + 128 * PJ;            // 4 * DI * EPS  (swizzled blocks)
    float* hp  = xs + 4 * DI * EPS;         // 4 * 128 * EPS (swizzled blocks)
    float* sb  = hp + 4 * 128 * EPS;        // 128

    const int tid = threadIdx.x;

    // ---- one-time weight/bias staging ----
    for (int idx = tid; idx < 128 * DI; idx += 256) {
        int j = idx / DI, i = idx - j * DI;
        W1t[i * PJ + j] = W1[idx];
    }
    for (int idx = tid; idx < 128 * 128; idx += 256) {
        int j = idx >> 7, i = idx & 127;
        W2t[i * PJ + j] = W2[idx];
    }
    if (tid < 128) sb[tid] = b1[tid];

    const int sub = tid >> 6;
    const int j2  = tid & 63;
    const float* xsb = xs + sub * (DI * EPS);
    float* hpb = hp + sub * (128 * EPS);
    const int sH = j2 & 7;                  // hp write swizzle (block j2)

    for (int tile = blockIdx.x; tile < NTILE; tile += gridDim.x) {
        const int e0 = tile * TEB;
        __syncthreads();   // previous tile's readers done before re-staging xs
        // Stage X tile: one 16B chunk (4 edges, one column i) per iteration.
        // 4 coalesced streaming LDG.32 transpose on the fly (X is read-once);
        // STS.128 at swizzled slot.
        for (int idx = tid; idx < 16 * DI; idx += 256) {
            int i  = idx % DI;       // column
            int t  = idx / DI;       // 0..15
            int c2 = t & 3, sb_ = t >> 2;
            const float* xp = X + (size_t)(e0 + sb_ * EPS + 4 * c2) * DI + i;
            float4 v = make_float4(__ldcs(xp), __ldcs(xp + DI),
                                   __ldcs(xp + 2 * DI), __ldcs(xp + 3 * DI));
            *(float4*)(xs + sb_ * (DI * EPS) + XOFF(i, c2)) = v;
        }
        __syncthreads();

        u64 accA[8], accB[8];
        {
            float bA = sb[2 * j2], bB = sb[2 * j2 + 1];
            u64 pA = pk2(bA, bA), pB = pk2(bB, bB);
#pragma unroll
            for (int p = 0; p < 8; p++) { accA[p] = pA; accB[p] = pB; }
        }

        // Layer 1 — unroll 16 so XOFF slot terms are compile-time immediates
        for (int ii = 0; ii < DI; ii += 16) {
            const float* xr = xsb + (ii >> 1) * 32;
            const float* wr = &W1t[ii * PJ + 2 * j2];
#pragma unroll
            for (int u = 0; u < 16; u++) {
                const int ro = (u >> 1) * 32;
                const int q4 = (u & 1) << 2;
                const int s  = (u >> 1) & 7;
                u64 wp = *(const u64*)&wr[u * PJ];
                float w0, w1; upk2(wp, w0, w1);
                u64 wa = pk2(w0, w0), wb = pk2(w1, w1);
                const ulonglong2 x01 = *(const ulonglong2*)&xr[ro + 4 * ((q4 | 0) ^ s)];
                const ulonglong2 x23 = *(const ulonglong2*)&xr[ro + 4 * ((q4 | 1) ^ s)];
                const ulonglong2 x45 = *(const ulonglong2*)&xr[ro + 4 * ((q4 | 2) ^ s)];
                const ulonglong2 x67 = *(const ulonglong2*)&xr[ro + 4 * ((q4 | 3) ^ s)];
                accA[0] = fma2(wa, x01.x, accA[0]); accB[0] = fma2(wb, x01.x, accB[0]);
                accA[1] = fma2(wa, x01.y, accA[1]); accB[1] = fma2(wb, x01.y, accB[1]);
                accA[2] = fma2(wa, x23.x, accA[2]); accB[2] = fma2(wb, x23.x, accB[2]);
                accA[3] = fma2(wa, x23.y, accA[3]); accB[3] = fma2(wb, x23.y, accB[3]);
                accA[4] = fma2(wa, x45.x, accA[4]); accB[4] = fma2(wb, x45.x, accB[4]);
                accA[5] = fma2(wa, x45.y, accA[5]); accB[5] = fma2(wb, x45.y, accB[5]);
                accA[6] = fma2(wa, x67.x, accA[6]); accB[6] = fma2(wb, x67.x, accB[6]);
                accA[7] = fma2(wa, x67.y, accA[7]); accB[7] = fma2(wb, x67.y, accB[7]);
            }
        }
        // hp writes: rows 2j2 (accA) and 2j2+1 (accB) = block j2; STS.128 at
        // swizzled slots -> full-bank spread, floor wavefronts.
        {
            float* hrow = hpb + j2 * 32;
#pragma unroll
            for (int c = 0; c < 4; c++) {
                float a0, a1, a2, a3, b0, b1, b2, b3;
                upk2(accA[2 * c], a0, a1); upk2(accA[2 * c + 1], a2, a3);
                upk2(accB[2 * c], b0, b1); upk2(accB[2 * c + 1], b2, b3);
                *(float4*)&hrow[4 * ((0 | c) ^ sH)] =
                    make_float4(lsig(a0), lsig(a1), lsig(a2), lsig(a3));
                *(float4*)&hrow[4 * ((4 | c) ^ sH)] =
                    make_float4(lsig(b0), lsig(b1), lsig(b2), lsig(b3));
            }
        }
        __syncthreads();

        // Layer 2 (no bias) — same unroll-16 swizzled reads from hp
#pragma unroll
        for (int p = 0; p < 8; p++) { accA[p] = 0ull; accB[p] = 0ull; }
        for (int ii = 0; ii < 128; ii += 16) {
            const float* xr = hpb + (ii >> 1) * 32;
            const float* wr = &W2t[ii * PJ + 2 * j2];
#pragma unroll
            for (int u = 0; u < 16; u++) {
                const int ro = (u >> 1) * 32;
                const int q4 = (u & 1) << 2;
                const int s  = (u >> 1) & 7;
                u64 wp = *(const u64*)&wr[u * PJ];
                float w0, w1; upk2(wp, w0, w1);
                u64 wa = pk2(w0, w0), wb = pk2(w1, w1);
                const ulonglong2 x01 = *(const ulonglong2*)&xr[ro + 4 * ((q4 | 0) ^ s)];
                const ulonglong2 x23 = *(const ulonglong2*)&xr[ro + 4 * ((q4 | 1) ^ s)];
                const ulonglong2 x45 = *(const ulonglong2*)&xr[ro + 4 * ((q4 | 2) ^ s)];
                const ulonglong2 x67 = *(const ulonglong2*)&xr[ro + 4 * ((q4 | 3) ^ s)];
                accA[0] = fma2(wa, x01.x, accA[0]); accB[0] = fma2(wb, x01.x, accB[0]);
                accA[1] = fma2(wa, x01.y, accA[1]); accB[1] = fma2(wb, x01.y, accB[1]);
                accA[2] = fma2(wa, x23.x, accA[2]); accB[2] = fma2(wb, x23.x, accB[2]);
                accA[3] = fma2(wa, x23.y, accA[3]); accB[3] = fma2(wb, x23.y, accB[3]);
                accA[4] = fma2(wa, x45.x, accA[4]); accB[4] = fma2(wb, x45.x, accB[4]);
                accA[5] = fma2(wa, x45.y, accA[5]); accB[5] = fma2(wb, x45.y, accB[5]);
                accA[6] = fma2(wa, x67.x, accA[6]); accB[6] = fma2(wb, x67.x, accB[6]);
                accA[7] = fma2(wa, x67.y, accA[7]); accB[7] = fma2(wb, x67.y, accB[7]);
            }
        }
#pragma unroll
        for (int p = 0; p < 8; p++) {
            float a0, a1, b0, b1;
            upk2(accA[p], a0, a1); upk2(accB[p], b0, b1);
            const int ea = e0 + sub * EPS + 2 * p;
            float2 v0 = make_float2(lsig(a0), lsig(b0));
            float2 v1 = make_float2(lsig(a1), lsig(b1));
            float2* o0 = (float2*)&out[(size_t)ea * 128 + 2 * j2];
            float2* o1 = (float2*)&out[(size_t)(ea + 1) * 128 + 2 * j2];
            if (STREAM_OUT) { __stcs(o0, v0); __stcs(o1, v1); }
            else            { *o0 = v0;       *o1 = v1;       }
        }
    }
}

// ---------------------------------------------------------------------------
// node[n] = sum_e mask[n,e] * s[e]   (mask entries are exactly 0 or 1)
// AND emit node-major bitmask g_bits[n][e/32] as a side product.
// One block per node; 4 warps each own a quarter row. Mask loads front-
// batched 4-deep (MLP_p1=4) and STREAMED (__ldcs: read-once data, keep L2
// for the g_s gathers). No atomics, fixed summation order.
// ---------------------------------------------------------------------------
__global__ void __launch_bounds__(128) k_node_agg(const float* __restrict__ mask)
{
    const int n    = blockIdx.x;
    const int w    = threadIdx.x >> 5;
    const int lane = threadIdx.x & 31;
    const float* mrow = mask + (size_t)n * E_TOT;
    float4 acc = make_float4(0.f, 0.f, 0.f, 0.f);

    const int ew0 = w * 256;           // first bit-word of this warp's quarter
    for (int it = 0; it < 256; it += 4) {
        // 4 independent coalesced streaming loads issued before any consumer
        float m0 = __ldcs(&mrow[(ew0 + it + 0) * 32 + lane]);
        float m1 = __ldcs(&mrow[(ew0 + it + 1) * 32 + lane]);
        float m2 = __ldcs(&mrow[(ew0 + it + 2) * 32 + lane]);
        float m3 = __ldcs(&mrow[(ew0 + it + 3) * 32 + lane]);
        float mg[4] = { m0, m1, m2, m3 };
#pragma unroll
        for (int q = 0; q < 4; q++) {
            const int ebase = (ew0 + it + q) * 32;
            unsigned bm = __ballot_sync(0xffffffffu, mg[q] != 0.0f);
            if (lane == 0) g_bits[n * (E_TOT / 32) + ew0 + it + q] = bm;
            while (bm) {
                int b = __ffs(bm) - 1; bm &= bm - 1;
                const float4 sv = *(const float4*)(g_s + (size_t)(ebase + b) * D + lane * 4);
                acc.x += sv.x; acc.y += sv.y; acc.z += sv.z; acc.w += sv.w;
            }
        }
    }

    __shared__ float red[4][128];
    red[w][lane * 4 + 0] = acc.x;
    red[w][lane * 4 + 1] = acc.y;
    red[w][lane * 4 + 2] = acc.z;
    red[w][lane * 4 + 3] = acc.w;
    __syncthreads();
    if (threadIdx.x < 128) {
        int t = threadIdx.x;
        g_node[(size_t)n * D + t] = red[0][t] + red[1][t] + red[2][t] + red[3][t];
    }
}

// ---------------------------------------------------------------------------
// Bit transpose: g_bits[n][we] -> g_bitsT[j][e]  (j = node-word = n/32)
// Warp tile = 32 nodes x 128 edges. uint4 streaming load per lane (g_bits is
// read-once), 128 ballots, coalesced 128B stores (lane b holds ballot of bit b).
// ---------------------------------------------------------------------------
__global__ void __launch_bounds__(256) k_bit_transpose()
{
    const int wg   = (blockIdx.x * blockDim.x + threadIdx.x) >> 5; // 0..16383
    const int lane = threadIdx.x & 31;
    const int nb   = wg >> 8;        // 0..63   (node-word j)
    const int we4  = wg & 255;       // 0..255  (uint4 index within row)

    const uint4 v = __ldcs(&((const uint4*)g_bits)[(size_t)(nb * 32 + lane) * 256 + we4]);
    unsigned wk[4] = { v.x, v.y, v.z, v.w };

#pragma unroll
    for (int k = 0; k < 4; k++) {
        unsigned mine = 0;
#pragma unroll
        for (int b = 0; b < 32; b++) {
            unsigned ob = __ballot_sync(0xffffffffu, (wk[k] >> b) & 1u);
            if (b == lane) mine = ob;
        }
        g_bitsT[(size_t)nb * E_TOT + we4 * 128 + k * 32 + lane] = mine;
    }
}

// ---------------------------------------------------------------------------
// cat[e] = [ sum_{n in bits(e)} node[n] - s[e] , feature[e] ]
// One warp per edge. Bit-words loaded 4-deep (front-batched, uniform) so L2
// latency overlaps; s/feature loads hoisted (streaming: both read-once) so
// they overlap the whole walk. g_node gathers hit L2 (1 MB resident).
// Fixed summation order, no atomics.
// ---------------------------------------------------------------------------
__global__ void __launch_bounds__(256) k_edge_agg(const float* __restrict__ feature)
{
    const int w    = threadIdx.x >> 5;
    const int lane = threadIdx.x & 31;
    const int e    = blockIdx.x * 8 + w;

    // hoisted: independent of the bitmask walk, overlaps it entirely
    const float4 sv = __ldcs((const float4*)(g_s + (size_t)e * D + lane * 4));
    float4 fv = make_float4(0.f, 0.f, 0.f, 0.f);
    if (lane < 8) fv = __ldcs((const float4*)(feature + (size_t)e * DF + lane * 4));

    float4 acc = make_float4(0.f, 0.f, 0.f, 0.f);
    const unsigned* brow = g_bitsT;  // [j][e]

    for (int j = 0; j < NN / 32; j += 4) {
        // 4 independent uniform loads issued before any consumer
        unsigned b0 = brow[(size_t)(j + 0) * E_TOT + e];
        unsigned b1 = brow[(size_t)(j + 1) * E_TOT + e];
        unsigned b2 = brow[(size_t)(j + 2) * E_TOT + e];
        unsigned b3 = brow[(size_t)(j + 3) * E_TOT + e];
        unsigned bw[4] = { b0, b1, b2, b3 };
#pragma unroll
        for (int q = 0; q < 4; q++) {
            unsigned bm = bw[q];
            const int nbase = (j + q) * 32;
            while (bm) {
                int b = __ffs(bm) - 1; bm &= bm - 1;
                int n = nbase + b;
                const float4 nv = *(const float4*)(g_node + (size_t)n * D + lane * 4);
                acc.x += nv.x; acc.y += nv.y; acc.z += nv.z; acc.w += nv.w;
            }
        }
    }
    acc.x -= sv.x; acc.y -= sv.y; acc.z -= sv.z; acc.w -= sv.w;
    *(float4*)(g_cat + (size_t)e * DC + lane * 4) = acc;
    if (lane < 8) {
        *(float4*)(g_cat + (size_t)e * DC + D + lane * 4) = fv;
    }
}

// ---------------------------------------------------------------------------
extern "C" void kernel_launch(void* const* d_in, const int* in_sizes, int n_in,
                              void* d_out, int out_size)
{
    const float* state   = (const float*)d_in[0];
    const float* feature = (const float*)d_in[1];
    const float* mask    = (const float*)d_in[2];
    // d_in[3] = mask_transpose: guaranteed == mask.T, derived on-chip instead
    const float* W1m     = (const float*)d_in[4];
    const float* b1m     = (const float*)d_in[5];
    const float* W2m     = (const float*)d_in[6];
    const float* W1a     = (const float*)d_in[7];
    const float* b1a     = (const float*)d_in[8];
    const float* W2a     = (const float*)d_in[9];
    float* out = (float*)d_out;

    float *s_dev = nullptr, *cat_dev = nullptr;
    cudaGetSymbolAddress((void**)&s_dev, g_s);      // immediate API, capture-safe
    cudaGetSymbolAddress((void**)&cat_dev, g_cat);

    const int SMEM_A = (128 * PJ + 128 * PJ + 4 * 128 * EPS + 4 * 128 * EPS + 128) * 4; // 199168 B
    const int SMEM_D = (160 * PJ + 128 * PJ + 4 * 160 * EPS + 4 * 128 * EPS + 128) * 4; // 224000 B
    cudaFuncSetAttribute(k_mlp<128, false>, cudaFuncAttributeMaxDynamicSharedMemorySize, SMEM_A);
    cudaFuncSetAttribute(k_mlp<160, true>,  cudaFuncAttributeMaxDynamicSharedMemorySize, SMEM_D);

    // s = lsig(lsig(state @ W1m^T + b1m) @ W2m^T)      (persistent, 1 CTA/SM)
    k_mlp<128, false><<<GRID_MLP, 256, SMEM_A>>>(state, W1m, b1m, W2m, s_dev);
    // node = mask @ s   (+ emit node-major bitmask)
    k_node_agg<<<NN, 128>>>(mask);
    // bitmask transpose (node-major -> edge-major)
    k_bit_transpose<<<2048, 256>>>();
    // cat = [maskT @ node - s, feature]   (maskT via bitmask)
    k_edge_agg<<<E_TOT / 8, 256>>>(feature);
    // out = lsig(lsig(cat @ W1a^T + b1a) @ W2a^T)      (persistent, 1 CTA/SM)
    k_mlp<160, true><<<GRID_MLP, 256, SMEM_D>>>(cat_dev, W1a, b1a, W2a, out);
}

// round 14
// speedup vs baseline: 1.0327x; 1.0327x over previous
#include <cuda_runtime.h>

#define E_TOT   32768
#define NN      2048
#define D       128
#define DF      32
#define DC      160
#define PJ      130   // weight shared pitch (conflict-free LDS.64)
#define EPS     16    // edges per sub (16 floats = 64B row; 2 rows = one 128B block)
#define TEB     64    // tile edges per block (4 subs x EPS)
#define GRID_MLP 152  // one persistent CTA per GB300 SM
#define NTILE   (E_TOT / TEB)   // 512 edge tiles

// Scratch (device globals: no allocations allowed)
__device__ float    g_s[E_TOT * D];        // 16 MB
__device__ float    g_cat[E_TOT * DC];     // 21 MB
__device__ float    g_node[NN * D];        // 1 MB (L2-resident)
__device__ unsigned g_bits[NN * (E_TOT / 32)];   // 8 MB  node-major bitmask
__device__ unsigned g_bitsE[E_TOT * (NN / 32)];  // 8 MB  EDGE-major: [e][j]

typedef unsigned long long u64;

__device__ __forceinline__ u64 pk2(float lo, float hi) {
    u64 r; asm("mov.b64 %0, {%1,%2};" : "=l"(r) : "f"(lo), "f"(hi)); return r;
}
__device__ __forceinline__ void upk2(u64 v, float& lo, float& hi) {
    asm("mov.b64 {%0,%1}, %2;" : "=f"(lo), "=f"(hi) : "l"(v));
}
// Packed fp32x2 FMA — 2x FFMA throughput on sm_103a (FFMA2), only via PTX.
__device__ __forceinline__ u64 fma2(u64 a, u64 b, u64 c) {
    u64 d; asm("fma.rn.f32x2 %0, %1, %2, %3;" : "=l"(d) : "l"(a), "l"(b), "l"(c)); return d;
}

// log_sigmoid(x) = min(x,0) - log1p(exp(-|x|))  (stable, matches jax.nn.log_sigmoid)
__device__ __forceinline__ float lsig(float x) {
    return fminf(x, 0.0f) - log1pf(__expf(-fabsf(x)));
}

// Swizzled chunk offset (in floats) for row i, 16B-chunk c, within a sub's
// region: block = i>>1 (2 rows = 32 floats = 128B), slot = ((i&1)*4 + c) ^ (block&7).
#define XOFF(i, c) (((i) >> 1) * 32 + 4 * (((((i) & 1) << 2) | (c)) ^ (((i) >> 1) & 7)))

// ---------------------------------------------------------------------------
// Persistent fused 2-layer MLP:  out = lsig( lsig(X @ W1^T + b1) @ W2^T )
// Grid = 152 CTAs (1/SM). Weights staged to shared ONCE; each CTA strides
// over 64-edge tiles. Block = 256 threads = 4 subs x 64 j2-threads.
// xs/hp use the XOR-swizzled chunk layout -> smem store phases at floor.
// ---------------------------------------------------------------------------
template <int DI, bool STREAM_OUT>
__global__ void __launch_bounds__(256) k_mlp(const float* __restrict__ X,
                                             const float* __restrict__ W1,
                                             const float* __restrict__ b1,
                                             const float* __restrict__ W2,
                                             float* __restrict__ out)
{
    extern __shared__ float sm[];
    float* W1t = sm;                        // DI * PJ
    float* W2t = W1t + DI * PJ;             // 128 * PJ
    float* xs  = W2t + 128 * PJ;            // 4 * DI * EPS  (swizzled blocks)
    float* hp  = xs + 4 * DI * EPS;         // 4 * 128 * EPS (swizzled blocks)
    float* sb  = hp + 4 * 128 * EPS;        // 128

    const int tid = threadIdx.x;

    for (int idx = tid; idx < 128 * DI; idx += 256) {
        int j = idx / DI, i = idx - j * DI;
        W1t[i * PJ + j] = W1[idx];
    }
    for (int idx = tid; idx < 128 * 128; idx += 256) {
        int j = idx >> 7, i = idx & 127;
        W2t[i * PJ + j] = W2[idx];
    }
    if (tid < 128) sb[tid] = b1[tid];

    const int sub = tid >> 6;
    const int j2  = tid & 63;
    const float* xsb = xs + sub * (DI * EPS);
    float* hpb = hp + sub * (128 * EPS);
    const int sH = j2 & 7;                  // hp write swizzle (block j2)

    for (int tile = blockIdx.x; tile < NTILE; tile += gridDim.x) {
        const int e0 = tile * TEB;
        __syncthreads();   // previous tile's readers done before re-staging xs
        for (int idx = tid; idx < 16 * DI; idx += 256) {
            int i  = idx % DI;       // column
            int t  = idx / DI;       // 0..15
            int c2 = t & 3, sb_ = t >> 2;
            const float* xp = X + (size_t)(e0 + sb_ * EPS + 4 * c2) * DI + i;
            float4 v = make_float4(__ldcs(xp), __ldcs(xp + DI),
                                   __ldcs(xp + 2 * DI), __ldcs(xp + 3 * DI));
            *(float4*)(xs + sb_ * (DI * EPS) + XOFF(i, c2)) = v;
        }
        __syncthreads();

        u64 accA[8], accB[8];
        {
            float bA = sb[2 * j2], bB = sb[2 * j2 + 1];
            u64 pA = pk2(bA, bA), pB = pk2(bB, bB);
#pragma unroll
            for (int p = 0; p < 8; p++) { accA[p] = pA; accB[p] = pB; }
        }

        // Layer 1 — unroll 16 so XOFF slot terms are compile-time immediates
        for (int ii = 0; ii < DI; ii += 16) {
            const float* xr = xsb + (ii >> 1) * 32;
            const float* wr = &W1t[ii * PJ + 2 * j2];
#pragma unroll
            for (int u = 0; u < 16; u++) {
                const int ro = (u >> 1) * 32;
                const int q4 = (u & 1) << 2;
                const int s  = (u >> 1) & 7;
                u64 wp = *(const u64*)&wr[u * PJ];
                float w0, w1; upk2(wp, w0, w1);
                u64 wa = pk2(w0, w0), wb = pk2(w1, w1);
                const ulonglong2 x01 = *(const ulonglong2*)&xr[ro + 4 * ((q4 | 0) ^ s)];
                const ulonglong2 x23 = *(const ulonglong2*)&xr[ro + 4 * ((q4 | 1) ^ s)];
                const ulonglong2 x45 = *(const ulonglong2*)&xr[ro + 4 * ((q4 | 2) ^ s)];
                const ulonglong2 x67 = *(const ulonglong2*)&xr[ro + 4 * ((q4 | 3) ^ s)];
                accA[0] = fma2(wa, x01.x, accA[0]); accB[0] = fma2(wb, x01.x, accB[0]);
                accA[1] = fma2(wa, x01.y, accA[1]); accB[1] = fma2(wb, x01.y, accB[1]);
                accA[2] = fma2(wa, x23.x, accA[2]); accB[2] = fma2(wb, x23.x, accB[2]);
                accA[3] = fma2(wa, x23.y, accA[3]); accB[3] = fma2(wb, x23.y, accB[3]);
                accA[4] = fma2(wa, x45.x, accA[4]); accB[4] = fma2(wb, x45.x, accB[4]);
                accA[5] = fma2(wa, x45.y, accA[5]); accB[5] = fma2(wb, x45.y, accB[5]);
                accA[6] = fma2(wa, x67.x, accA[6]); accB[6] = fma2(wb, x67.x, accB[6]);
                accA[7] = fma2(wa, x67.y, accA[7]); accB[7] = fma2(wb, x67.y, accB[7]);
            }
        }
        {
            float* hrow = hpb + j2 * 32;
#pragma unroll
            for (int c = 0; c < 4; c++) {
                float a0, a1, a2, a3, b0, b1, b2, b3;
                upk2(accA[2 * c], a0, a1); upk2(accA[2 * c + 1], a2, a3);
                upk2(accB[2 * c], b0, b1); upk2(accB[2 * c + 1], b2, b3);
                *(float4*)&hrow[4 * ((0 | c) ^ sH)] =
                    make_float4(lsig(a0), lsig(a1), lsig(a2), lsig(a3));
                *(float4*)&hrow[4 * ((4 | c) ^ sH)] =
                    make_float4(lsig(b0), lsig(b1), lsig(b2), lsig(b3));
            }
        }
        __syncthreads();

        // Layer 2 (no bias)
#pragma unroll
        for (int p = 0; p < 8; p++) { accA[p] = 0ull; accB[p] = 0ull; }
        for (int ii = 0; ii < 128; ii += 16) {
            const float* xr = hpb + (ii >> 1) * 32;
            const float* wr = &W2t[ii * PJ + 2 * j2];
#pragma unroll
            for (int u = 0; u < 16; u++) {
                const int ro = (u >> 1) * 32;
                const int q4 = (u & 1) << 2;
                const int s  = (u >> 1) & 7;
                u64 wp = *(const u64*)&wr[u * PJ];
                float w0, w1; upk2(wp, w0, w1);
                u64 wa = pk2(w0, w0), wb = pk2(w1, w1);
                const ulonglong2 x01 = *(const ulonglong2*)&xr[ro + 4 * ((q4 | 0) ^ s)];
                const ulonglong2 x23 = *(const ulonglong2*)&xr[ro + 4 * ((q4 | 1) ^ s)];
                const ulonglong2 x45 = *(const ulonglong2*)&xr[ro + 4 * ((q4 | 2) ^ s)];
                const ulonglong2 x67 = *(const ulonglong2*)&xr[ro + 4 * ((q4 | 3) ^ s)];
                accA[0] = fma2(wa, x01.x, accA[0]); accB[0] = fma2(wb, x01.x, accB[0]);
                accA[1] = fma2(wa, x01.y, accA[1]); accB[1] = fma2(wb, x01.y, accB[1]);
                accA[2] = fma2(wa, x23.x, accA[2]); accB[2] = fma2(wb, x23.x, accB[2]);
                accA[3] = fma2(wa, x23.y, accA[3]); accB[3] = fma2(wb, x23.y, accB[3]);
                accA[4] = fma2(wa, x45.x, accA[4]); accB[4] = fma2(wb, x45.x, accB[4]);
                accA[5] = fma2(wa, x45.y, accA[5]); accB[5] = fma2(wb, x45.y, accB[5]);
                accA[6] = fma2(wa, x67.x, accA[6]); accB[6] = fma2(wb, x67.x, accB[6]);
                accA[7] = fma2(wa, x67.y, accA[7]); accB[7] = fma2(wb, x67.y, accB[7]);
            }
        }
#pragma unroll
        for (int p = 0; p < 8; p++) {
            float a0, a1, b0, b1;
            upk2(accA[p], a0, a1); upk2(accB[p], b0, b1);
            const int ea = e0 + sub * EPS + 2 * p;
            float2 v0 = make_float2(lsig(a0), lsig(b0));
            float2 v1 = make_float2(lsig(a1), lsig(b1));
            float2* o0 = (float2*)&out[(size_t)ea * 128 + 2 * j2];
            float2* o1 = (float2*)&out[(size_t)(ea + 1) * 128 + 2 * j2];
            if (STREAM_OUT) { __stcs(o0, v0); __stcs(o1, v1); }
            else            { *o0 = v0;       *o1 = v1;       }
        }
    }
}

// ---------------------------------------------------------------------------
// node[n] = sum_e mask[n,e] * s[e]   (+ node-major bitmask side product)
// ---------------------------------------------------------------------------
__global__ void __launch_bounds__(128) k_node_agg(const float* __restrict__ mask)
{
    const int n    = blockIdx.x;
    const int w    = threadIdx.x >> 5;
    const int lane = threadIdx.x & 31;
    const float* mrow = mask + (size_t)n * E_TOT;
    float4 acc = make_float4(0.f, 0.f, 0.f, 0.f);

    const int ew0 = w * 256;           // first bit-word of this warp's quarter
    for (int it = 0; it < 256; it += 4) {
        float m0 = __ldcs(&mrow[(ew0 + it + 0) * 32 + lane]);
        float m1 = __ldcs(&mrow[(ew0 + it + 1) * 32 + lane]);
        float m2 = __ldcs(&mrow[(ew0 + it + 2) * 32 + lane]);
        float m3 = __ldcs(&mrow[(ew0 + it + 3) * 32 + lane]);
        float mg[4] = { m0, m1, m2, m3 };
#pragma unroll
        for (int q = 0; q < 4; q++) {
            const int ebase = (ew0 + it + q) * 32;
            unsigned bm = __ballot_sync(0xffffffffu, mg[q] != 0.0f);
            if (lane == 0) g_bits[n * (E_TOT / 32) + ew0 + it + q] = bm;
            while (bm) {
                int b = __ffs(bm) - 1; bm &= bm - 1;
                const float4 sv = *(const float4*)(g_s + (size_t)(ebase + b) * D + lane * 4);
                acc.x += sv.x; acc.y += sv.y; acc.z += sv.z; acc.w += sv.w;
            }
        }
    }

    __shared__ float red[4][128];
    red[w][lane * 4 + 0] = acc.x;
    red[w][lane * 4 + 1] = acc.y;
    red[w][lane * 4 + 2] = acc.z;
    red[w][lane * 4 + 3] = acc.w;
    __syncthreads();
    if (threadIdx.x < 128) {
        int t = threadIdx.x;
        g_node[(size_t)n * D + t] = red[0][t] + red[1][t] + red[2][t] + red[3][t];
    }
}

// ---------------------------------------------------------------------------
// Bit transpose: g_bits[n][we] -> g_bitsE[e][j]  (EDGE-major rows, 256B/edge)
// Warp tile = 32 nodes x 128 edges. uint4 streaming load, 128 ballots.
// Stores are scattered 4B (stride 256B) but land in L2 (8MB region).
// ---------------------------------------------------------------------------
__global__ void __launch_bounds__(256) k_bit_transpose()
{
    const int wg   = (blockIdx.x * blockDim.x + threadIdx.x) >> 5; // 0..16383
    const int lane = threadIdx.x & 31;
    const int nb   = wg >> 8;        // 0..63   (node-word j)
    const int we4  = wg & 255;       // 0..255  (uint4 index within row)

    const uint4 v = __ldcs(&((const uint4*)g_bits)[(size_t)(nb * 32 + lane) * 256 + we4]);
    unsigned wk[4] = { v.x, v.y, v.z, v.w };

#pragma unroll
    for (int k = 0; k < 4; k++) {
        unsigned mine = 0;
#pragma unroll
        for (int b = 0; b < 32; b++) {
            unsigned ob = __ballot_sync(0xffffffffu, (wk[k] >> b) & 1u);
            if (b == lane) mine = ob;
        }
        // edge = we4*128 + k*32 + lane holds node-word nb
        g_bitsE[(size_t)(we4 * 128 + k * 32 + lane) * (NN / 32) + nb] = mine;
    }
}

// ---------------------------------------------------------------------------
// cat[e] = [ sum_{n in bits(e)} node[n] - s[e] , feature[e] ]
// One warp per edge. The ENTIRE 64-word bit row is fetched with one
// coalesced uint2-per-lane load (2 lines); the walk is register-only via
// shfl broadcasts -> no memory stalls in the bit scan. Two alternating
// accumulators break the FADD chain. Fixed order, no atomics.
// ---------------------------------------------------------------------------
__global__ void __launch_bounds__(256) k_edge_agg(const float* __restrict__ feature)
{
    const int w    = threadIdx.x >> 5;
    const int lane = threadIdx.x & 31;
    const int e    = blockIdx.x * 8 + w;

    // whole bit row: lane holds words 2*lane (x) and 2*lane+1 (y)
    const uint2 mw = ((const uint2*)(g_bitsE + (size_t)e * (NN / 32)))[lane];

    // hoisted, streaming (read-once): overlap the whole walk
    const float4 sv = __ldcs((const float4*)(g_s + (size_t)e * D + lane * 4));
    float4 fv = make_float4(0.f, 0.f, 0.f, 0.f);
    if (lane < 8) fv = __ldcs((const float4*)(feature + (size_t)e * DF + lane * 4));

    float4 acc0 = make_float4(0.f, 0.f, 0.f, 0.f);
    float4 acc1 = make_float4(0.f, 0.f, 0.f, 0.f);

#pragma unroll 4
    for (int jw = 0; jw < 32; jw++) {
        unsigned w0 = __shfl_sync(0xffffffffu, mw.x, jw);
        unsigned w1 = __shfl_sync(0xffffffffu, mw.y, jw);
        const int nb0 = jw * 64;       // word 2*jw   -> nodes [jw*64, jw*64+32)
        while (w0) {
            int b = __ffs(w0) - 1; w0 &= w0 - 1;
            const float4 nv = *(const float4*)(g_node + (size_t)(nb0 + b) * D + lane * 4);
            acc0.x += nv.x; acc0.y += nv.y; acc0.z += nv.z; acc0.w += nv.w;
        }
        while (w1) {
            int b = __ffs(w1) - 1; w1 &= w1 - 1;
            const float4 nv = *(const float4*)(g_node + (size_t)(nb0 + 32 + b) * D + lane * 4);
            acc1.x += nv.x; acc1.y += nv.y; acc1.z += nv.z; acc1.w += nv.w;
        }
    }
    acc0.x += acc1.x; acc0.y += acc1.y; acc0.z += acc1.z; acc0.w += acc1.w;
    acc0.x -= sv.x;   acc0.y -= sv.y;   acc0.z -= sv.z;   acc0.w -= sv.w;
    *(float4*)(g_cat + (size_t)e * DC + lane * 4) = acc0;
    if (lane < 8) {
        *(float4*)(g_cat + (size_t)e * DC + D + lane * 4) = fv;
    }
}

// ---------------------------------------------------------------------------
extern "C" void kernel_launch(void* const* d_in, const int* in_sizes, int n_in,
                              void* d_out, int out_size)
{
    const float* state   = (const float*)d_in[0];
    const float* feature = (const float*)d_in[1];
    const float* mask    = (const float*)d_in[2];
    // d_in[3] = mask_transpose: guaranteed == mask.T, derived on-chip instead
    const float* W1m     = (const float*)d_in[4];
    const float* b1m     = (const float*)d_in[5];
    const float* W2m     = (const float*)d_in[6];
    const float* W1a     = (const float*)d_in[7];
    const float* b1a     = (const float*)d_in[8];
    const float* W2a     = (const float*)d_in[9];
    float* out = (float*)d_out;

    float *s_dev = nullptr, *cat_dev = nullptr;
    cudaGetSymbolAddress((void**)&s_dev, g_s);      // immediate API, capture-safe
    cudaGetSymbolAddress((void**)&cat_dev, g_cat);

    const int SMEM_A = (128 * PJ + 128 * PJ + 4 * 128 * EPS + 4 * 128 * EPS + 128) * 4; // 199168 B
    const int SMEM_D = (160 * PJ + 128 * PJ + 4 * 160 * EPS + 4 * 128 * EPS + 128) * 4; // 224000 B
    cudaFuncSetAttribute(k_mlp<128, false>, cudaFuncAttributeMaxDynamicSharedMemorySize, SMEM_A);
    cudaFuncSetAttribute(k_mlp<160, true>,  cudaFuncAttributeMaxDynamicSharedMemorySize, SMEM_D);

    // s = lsig(lsig(state @ W1m^T + b1m) @ W2m^T)      (persistent, 1 CTA/SM)
    k_mlp<128, false><<<GRID_MLP, 256, SMEM_A>>>(state, W1m, b1m, W2m, s_dev);
    // node = mask @ s   (+ emit node-major bitmask)
    k_node_agg<<<NN, 128>>>(mask);
    // bitmask transpose (node-major -> EDGE-major rows)
    k_bit_transpose<<<2048, 256>>>();
    // cat = [maskT @ node - s, feature]   (maskT via edge-major bit rows)
    k_edge_agg<<<E_TOT / 8, 256>>>(feature);
    // out = lsig(lsig(cat @ W1a^T + b1a) @ W2a^T)      (persistent, 1 CTA/SM)
    k_mlp<160, true><<<GRID_MLP, 256, SMEM_D>>>(cat_dev, W1a, b1a, W2a, out);
}